// round 5
// baseline (speedup 1.0000x reference)
#include <cuda_runtime.h>
#include <cuda_fp16.h>
#include <cstdint>

#define NB   16
#define NWAY 5
#define NQ   25
#define NSS  130
#define NQQ  75
#define CF   640
#define SRN  (NB*NWAY*NSS)   // 10400
#define TRN  (NB*NQQ*NQ)     // 30000
#define ROWB (CF*2)          // 1280 B per row (fp16)

__device__ __half g_Shi[SRN*CF];
__device__ __half g_Sps[SRN*CF];
__device__ __half g_Thi[TRN*CF];
__device__ __half g_Tps[TRN*CF];
__device__ float g_ss_sum[NB*NWAY];
__device__ float g_mmd_q[NB*NQQ];
__device__ float g_qs_sum[NB*NQQ*NWAY];

// ---------------------------------------------------------------------------
__device__ __forceinline__ uint32_t smem_u32(const void* p) {
    uint32_t a;
    asm("{ .reg .u64 t; cvta.to.shared.u64 t, %1; cvt.u32.u64 %0, t; }"
        : "=r"(a) : "l"(p));
    return a;
}
__device__ __forceinline__ void ldsm_x4(uint32_t* r, uint32_t addr) {
    asm volatile("ldmatrix.sync.aligned.m8n8.x4.shared.b16 {%0,%1,%2,%3}, [%4];"
                 : "=r"(r[0]), "=r"(r[1]), "=r"(r[2]), "=r"(r[3]) : "r"(addr));
}
__device__ __forceinline__ void mma4(float* c, const uint32_t* a,
                                     uint32_t b0, uint32_t b1) {
    asm volatile(
        "mma.sync.aligned.m16n8k16.row.col.f32.f16.f16.f32 "
        "{%0,%1,%2,%3}, {%4,%5,%6,%7}, {%8,%9}, {%0,%1,%2,%3};"
        : "+f"(c[0]), "+f"(c[1]), "+f"(c[2]), "+f"(c[3])
        : "r"(a[0]), "r"(a[1]), "r"(a[2]), "r"(a[3]), "r"(b0), "r"(b1));
}
__device__ __forceinline__ void cp16(uint32_t dst, const void* src, int szp) {
    asm volatile("cp.async.cg.shared.global [%0], [%1], 16, %2;"
                 :: "r"(dst), "l"(src), "r"(szp));
}
#define CP_COMMIT() asm volatile("cp.async.commit_group;" ::: "memory")
#define CP_WAIT1()  asm volatile("cp.async.wait_group 1;" ::: "memory")
#define CP_WAIT0()  asm volatile("cp.async.wait_group 0;" ::: "memory")

// acc = hihi*(1+1/1024) + residual ; dot = acc*1024/1025 ; d2 = 2 - 2*dot
__device__ __forceinline__ float multigauss_acc(float acc) {
    float d2 = fmaxf(2.0f - 1.9980487804878049f * acc, 0.0f);
    float u  = __expf(-0.125f * d2);
    float u2 = u*u, u4 = u2*u2, u8 = u4*u4, u16 = u8*u8;
    return u + u2 + u4 + u8 + u16;
}

// ---------------------------------------------------------------------------
__global__ void zero_kernel() {
    int t = blockIdx.x * blockDim.x + threadIdx.x;
    if (t < NB * NQQ * NWAY) g_qs_sum[t] = 0.f;
}

// normalize: ONE WARP PER ROW, no block barriers
__global__ __launch_bounds__(256) void norm_kernel(
    const float* __restrict__ sup, const float* __restrict__ qry) {
    int row = blockIdx.x * 8 + (threadIdx.x >> 5);
    if (row >= SRN + TRN) return;
    int lane = threadIdx.x & 31;

    const float* src;
    __half *dh, *dp;
    if (row < SRN) {
        src = sup + (size_t)row * CF;
        dh = g_Shi + (size_t)row * CF; dp = g_Sps + (size_t)row * CF;
    } else {
        int r = row - SRN;
        src = qry + (size_t)r * CF;
        dh = g_Thi + (size_t)r * CF; dp = g_Tps + (size_t)r * CF;
    }

    float4 v[5];
    float s1 = 0.f, s2 = 0.f;
#pragma unroll
    for (int s = 0; s < 5; s++) {
        v[s] = ((const float4*)src)[s * 32 + lane];
        s1 += v[s].x + v[s].y + v[s].z + v[s].w;
        s2 += v[s].x*v[s].x + v[s].y*v[s].y + v[s].z*v[s].z + v[s].w*v[s].w;
    }
#pragma unroll
    for (int o = 16; o > 0; o >>= 1) {
        s1 += __shfl_xor_sync(0xffffffffu, s1, o);
        s2 += __shfl_xor_sync(0xffffffffu, s2, o);
    }
    float mean = s1 * (1.0f / CF);
    float inv = rsqrtf(s2 - s1 * mean + 1e-12f);

#pragma unroll
    for (int s = 0; s < 5; s++) {
        float x[4] = {(v[s].x - mean) * inv, (v[s].y - mean) * inv,
                      (v[s].z - mean) * inv, (v[s].w - mean) * inv};
        union { __half h[4]; uint2 u; } ph, pp;
#pragma unroll
        for (int k = 0; k < 4; k++) {
            __half hh = __float2half_rn(x[k]);
            float h = __half2float(hh);
            ph.h[k] = hh;
            float P = h + 1024.0f * (x[k] - h);
            pp.h[k] = __float2half_rn(P * 0.03125f);
        }
        ((uint2*)dh)[s * 32 + lane] = ph.u;
        ((uint2*)dp)[s * 32 + lane] = pp.u;
    }
}

// ---------------------------------------------------------------------------
// cross Gram: CTA tile 128x128; 8 warps 4x2 warp tile 32x64
// 3-stage cp.async pipeline, chunk = 16 cols (32B rows, stride 48)
#define X_RB    48
#define X_ARR   (128*X_RB)         // 6144
#define X_STAGE (4*X_ARR)          // 24576
#define X_SMEM  (3*X_STAGE)        // 73728
#define X_CH    40

__global__ __launch_bounds__(256, 2) void cross_mma() {
    extern __shared__ char smem[];
    __shared__ float tab[16];
    uint32_t sb = smem_u32(smem);
    int tid = threadIdx.x, lane = tid & 31, wid = tid >> 5;
    int wm = wid >> 1, wn = wid & 1;
    int gid = lane >> 2, tig = lane & 3;

    int bx = blockIdx.x;
    int nt_t = bx % 15;
    int mt_t = (bx / 15) % 6;
    int b    = bx / 90;

    int aValid = 650 - mt_t * 128; if (aValid > 128) aValid = 128;
    int bValid = 1875 - nt_t * 128; if (bValid > 128) bValid = 128;
    const char* A0 = (const char*)(g_Shi + ((size_t)b * 650 + mt_t * 128) * CF);
    const char* A1 = (const char*)(g_Sps + ((size_t)b * 650 + mt_t * 128) * CF);
    const char* B0 = (const char*)(g_Thi + ((size_t)b * 1875 + nt_t * 128) * CF);
    const char* B1 = (const char*)(g_Tps + ((size_t)b * 1875 + nt_t * 128) * CF);

    if (tid < 16) tab[tid] = 0.f;

    float acc[2][8][4];
#pragma unroll
    for (int i = 0; i < 2; i++)
#pragma unroll
        for (int j = 0; j < 8; j++)
#pragma unroll
            for (int k = 0; k < 4; k++) acc[i][j][k] = 0.f;

    int lrow = lane & 15, lcol = (lane >> 4) << 4;

    auto fill = [&](int stage, int c) {
#pragma unroll
        for (int it = 0; it < 4; it++) {
            int idx = tid + it * 256;          // 0..1023
            int arr = idx >> 8;                // 0:Ahi 1:Aps 2:Bhi 3:Bps
            int rs  = idx & 255;
            int row = rs >> 1, seg = rs & 1;
            const char* base = (arr == 0) ? A0 : (arr == 1) ? A1
                             : (arr == 2) ? B0 : B1;
            int valid = (arr < 2) ? aValid : bValid;
            cp16(sb + stage * X_STAGE + arr * X_ARR + row * X_RB + seg * 16,
                 base + (size_t)row * ROWB + c * 32 + seg * 16,
                 row < valid ? 16 : 0);
        }
        CP_COMMIT();
    };

    fill(0, 0); fill(1, 1);
    for (int c = 0; c < X_CH; c++) {
        if (c == X_CH - 1) { CP_WAIT0(); } else { CP_WAIT1(); }
        __syncthreads();
        if (c + 2 < X_CH) fill((c + 2) % 3, c + 2);

        uint32_t base = sb + (c % 3) * X_STAGE;
        uint32_t ahi[2][4], aps[2][4];
#pragma unroll
        for (int mt = 0; mt < 2; mt++) {
            int ro = (wm * 32 + mt * 16 + lrow) * X_RB + lcol;
            ldsm_x4(ahi[mt], base + ro);
            ldsm_x4(aps[mt], base + X_ARR + ro);
        }
#pragma unroll
        for (int p = 0; p < 4; p++) {
            uint32_t bhi[4], bps[4];
            int ro = (wn * 64 + p * 16 + lrow) * X_RB + lcol;
            ldsm_x4(bhi, base + 2 * X_ARR + ro);
            ldsm_x4(bps, base + 3 * X_ARR + ro);
#pragma unroll
            for (int mt = 0; mt < 2; mt++) {
                mma4(acc[mt][p*2+0], ahi[mt], bhi[0], bhi[2]);
                mma4(acc[mt][p*2+0], aps[mt], bps[0], bps[2]);
                mma4(acc[mt][p*2+1], ahi[mt], bhi[1], bhi[3]);
                mma4(acc[mt][p*2+1], aps[mt], bps[1], bps[3]);
            }
        }
    }

    // epilogue: multigauss + (w,q) bucket reduction
    int qb = nt_t * 128;
    int q_base = qb / 25;
    int w_base = (mt_t * 128) / 130;
#pragma unroll
    for (int mt = 0; mt < 2; mt++)
#pragma unroll
    for (int rh = 0; rh < 2; rh++) {
        int row = wm * 32 + mt * 16 + rh * 8 + gid;
        int gs = mt_t * 128 + row;
        if (gs < 650) {
            int wrel = gs / 130 - w_base;
            float run = 0.f;
            int qprev = (qb + wn * 64 + tig * 2) / 25;
#pragma unroll
            for (int nt = 0; nt < 8; nt++)
#pragma unroll
            for (int e = 0; e < 2; e++) {
                int gt = qb + wn * 64 + nt * 8 + tig * 2 + e;
                int q = gt / 25;
                if (q != qprev) {
                    atomicAdd(&tab[wrel * 8 + (qprev - q_base)], run);
                    run = 0.f; qprev = q;
                }
                if (gt < 1875) run += multigauss_acc(acc[mt][nt][rh * 2 + e]);
            }
            atomicAdd(&tab[wrel * 8 + (qprev - q_base)], run);
        }
    }
    __syncthreads();
    if (tid < 16) {
        float v = tab[tid];
        if (v != 0.f) {
            int q = q_base + (tid & 7);
            int w = w_base + (tid >> 3);
            if (q < NQQ && w < NWAY)
                atomicAdd(&g_qs_sum[(b * NQQ + q) * NWAY + w], v);
        }
    }
}

// ---------------------------------------------------------------------------
// fused self Grams: blocks [0,80) -> kss (288 thr), [80,320) -> kqq (160 thr)
#define RB     80
#define CHS    20
#define SRT    144
#define S_STAGE (2*SRT*RB)         // 23040
#define S_SMEM  (2*S_STAGE)        // 46080
#define QRT    132
#define Q_STAGE (2*QRT*RB)         // 21120

__global__ __launch_bounds__(288) void self_mma() {
    extern __shared__ char smem[];
    __shared__ float red[9];
    uint32_t sb = smem_u32(smem);
    int tid = threadIdx.x, lane = tid & 31, wid = tid >> 5;
    int gid = lane >> 2, tig = lane & 3;
    int lrow = lane & 15, lcol = (lane >> 4) << 4;

    if (blockIdx.x < 80) {
        // ---- kss: CTA per (b,w); 9 warps 3x3, warp tile 48x48 ----
        int b = blockIdx.x / NWAY, w = blockIdx.x % NWAY;
        int wm = wid / 3, wn = wid % 3;
        const char* H = (const char*)(g_Shi + ((size_t)(b * NWAY + w) * NSS) * CF);
        const char* P = (const char*)(g_Sps + ((size_t)(b * NWAY + w) * NSS) * CF);

        for (int idx = tid; idx < 4 * 14 * 5; idx += 288) {
            int buf = idx / 70, rr = (idx % 70) / 5, sg = idx % 5;
            int st = buf >> 1, arr = buf & 1;
            *(uint4*)(smem + st * S_STAGE + arr * (SRT*RB) + (130 + rr) * RB + sg * 16)
                = make_uint4(0,0,0,0);
        }
        __syncthreads();

        float acc[3][6][4];
#pragma unroll
        for (int i = 0; i < 3; i++)
#pragma unroll
            for (int j = 0; j < 6; j++)
#pragma unroll
                for (int k = 0; k < 4; k++) acc[i][j][k] = 0.f;

        auto fill = [&](int stage, int c) {
#pragma unroll
            for (int it = 0; it < 4; it++) {
                int idx = tid + it * 288;
                if (idx < 1040) {
                    int arr = idx >= 520, rs = arr ? idx - 520 : idx;
                    int row = rs >> 2, seg = rs & 3;
                    const char* base = arr ? P : H;
                    cp16(sb + stage * S_STAGE + arr * (SRT*RB) + row * RB + seg * 16,
                         base + (size_t)row * ROWB + c * 64 + seg * 16, 16);
                }
            }
            CP_COMMIT();
        };

        fill(0, 0);
        for (int c = 0; c < CHS; c++) {
            if (c + 1 < CHS) { fill((c + 1) & 1, c + 1); CP_WAIT1(); }
            else            { CP_WAIT0(); }
            __syncthreads();
            uint32_t base = sb + (c & 1) * S_STAGE;
#pragma unroll
            for (int ks = 0; ks < 2; ks++) {
                uint32_t ahi[3][4], aps[3][4];
#pragma unroll
                for (int mt = 0; mt < 3; mt++) {
                    int ro = (wm * 48 + mt * 16 + lrow) * RB + ks * 32 + lcol;
                    ldsm_x4(ahi[mt], base + ro);
                    ldsm_x4(aps[mt], base + SRT*RB + ro);
                }
#pragma unroll
                for (int p = 0; p < 3; p++) {
                    uint32_t bhi[4], bps[4];
                    int ro = (wn * 48 + p * 16 + lrow) * RB + ks * 32 + lcol;
                    ldsm_x4(bhi, base + ro);
                    ldsm_x4(bps, base + SRT*RB + ro);
#pragma unroll
                    for (int mt = 0; mt < 3; mt++) {
                        mma4(acc[mt][p*2+0], ahi[mt], bhi[0], bhi[2]);
                        mma4(acc[mt][p*2+0], aps[mt], bps[0], bps[2]);
                        mma4(acc[mt][p*2+1], ahi[mt], bhi[1], bhi[3]);
                        mma4(acc[mt][p*2+1], aps[mt], bps[1], bps[3]);
                    }
                }
            }
            __syncthreads();
        }

        float sum = 0.f;
#pragma unroll
        for (int mt = 0; mt < 3; mt++)
#pragma unroll
        for (int nt = 0; nt < 6; nt++)
#pragma unroll
        for (int rh = 0; rh < 2; rh++)
#pragma unroll
        for (int e = 0; e < 2; e++) {
            int row = wm * 48 + mt * 16 + rh * 8 + gid;
            int col = wn * 48 + nt * 8 + tig * 2 + e;
            if (row < NSS && col < NSS && row != col)
                sum += multigauss_acc(acc[mt][nt][rh * 2 + e]);
        }
#pragma unroll
        for (int o = 16; o > 0; o >>= 1) sum += __shfl_down_sync(0xffffffffu, sum, o);
        if (lane == 0) red[wid] = sum;
        __syncthreads();
        if (tid == 0) {
            float t = 0.f;
            for (int i = 0; i < 9; i++) t += red[i];
            g_ss_sum[b * NWAY + w] = t;
        }
    } else {
        // ---- kqq: CTA per (b, 5-q group); warps 0..4 each do one 25x25 ----
        if (tid >= 160) return;
        int p = blockIdx.x - 80;
        int b = p / 15, qg = p % 15;
        const char* H = (const char*)(g_Thi + ((size_t)b * 1875 + qg * 125) * CF);
        const char* P = (const char*)(g_Tps + ((size_t)b * 1875 + qg * 125) * CF);

        for (int idx = tid; idx < 4 * 7 * 5; idx += 160) {
            int buf = idx / 35, rr = (idx % 35) / 5, sg = idx % 5;
            int st = buf >> 1, arr = buf & 1;
            *(uint4*)(smem + st * Q_STAGE + arr * (QRT*RB) + (125 + rr) * RB + sg * 16)
                = make_uint4(0,0,0,0);
        }
        __syncthreads();

        float acc[2][4][4];
#pragma unroll
        for (int i = 0; i < 2; i++)
#pragma unroll
            for (int j = 0; j < 4; j++)
#pragma unroll
                for (int k = 0; k < 4; k++) acc[i][j][k] = 0.f;

        int rbase = wid * 25;

        auto fill = [&](int stage, int c) {
#pragma unroll
            for (int it = 0; it < 7; it++) {
                int idx = tid + it * 160;
                if (idx < 1000) {
                    int arr = idx >= 500, rs = arr ? idx - 500 : idx;
                    int row = rs >> 2, seg = rs & 3;
                    const char* base = arr ? P : H;
                    cp16(sb + stage * Q_STAGE + arr * (QRT*RB) + row * RB + seg * 16,
                         base + (size_t)row * ROWB + c * 64 + seg * 16, 16);
                }
            }
            CP_COMMIT();
        };

        fill(0, 0);
        for (int c = 0; c < CHS; c++) {
            if (c + 1 < CHS) { fill((c + 1) & 1, c + 1); CP_WAIT1(); }
            else            { CP_WAIT0(); }
            __syncthreads();
            uint32_t base = sb + (c & 1) * Q_STAGE;
#pragma unroll
            for (int ks = 0; ks < 2; ks++) {
                uint32_t ahi[2][4], aps[2][4];
#pragma unroll
                for (int mt = 0; mt < 2; mt++) {
                    int ro = (rbase + mt * 16 + lrow) * RB + ks * 32 + lcol;
                    ldsm_x4(ahi[mt], base + ro);
                    ldsm_x4(aps[mt], base + QRT*RB + ro);
                }
#pragma unroll
                for (int pp = 0; pp < 2; pp++) {
                    uint32_t bhi[4], bps[4];
                    int ro = (rbase + pp * 16 + lrow) * RB + ks * 32 + lcol;
                    ldsm_x4(bhi, base + ro);
                    ldsm_x4(bps, base + QRT*RB + ro);
#pragma unroll
                    for (int mt = 0; mt < 2; mt++) {
                        mma4(acc[mt][pp*2+0], ahi[mt], bhi[0], bhi[2]);
                        mma4(acc[mt][pp*2+0], aps[mt], bps[0], bps[2]);
                        mma4(acc[mt][pp*2+1], ahi[mt], bhi[1], bhi[3]);
                        mma4(acc[mt][pp*2+1], aps[mt], bps[1], bps[3]);
                    }
                }
            }
            __syncthreads();
        }

        float sum = 0.f;
#pragma unroll
        for (int mt = 0; mt < 2; mt++)
#pragma unroll
        for (int nt = 0; nt < 4; nt++)
#pragma unroll
        for (int rh = 0; rh < 2; rh++)
#pragma unroll
        for (int e = 0; e < 2; e++) {
            int row = mt * 16 + rh * 8 + gid;
            int col = nt * 8 + tig * 2 + e;
            if (row < NQ && col < NQ && row != col)
                sum += multigauss_acc(acc[mt][nt][rh * 2 + e]);
        }
#pragma unroll
        for (int o = 16; o > 0; o >>= 1) sum += __shfl_down_sync(0xffffffffu, sum, o);
        if (lane == 0)
            g_mmd_q[b * NQQ + qg * 5 + wid] = sum * (1.0f / (NQ * (NQ - 1)));
    }
}

// ---------------------------------------------------------------------------
__global__ void combine_kernel(float* __restrict__ out) {
    int idx = blockIdx.x * blockDim.x + threadIdx.x;
    if (idx >= NB * NQQ * NWAY) return;
    int w = idx % NWAY;
    int bq = idx / NWAY;
    int b = bq / NQQ;
    out[idx] = g_ss_sum[b * NWAY + w] * (1.0f / (NSS * (NSS - 1)))
             + g_mmd_q[bq]
             - 2.0f * g_qs_sum[idx] * (1.0f / (NSS * NQ));
}

// ---------------------------------------------------------------------------
extern "C" void kernel_launch(void* const* d_in, const int* in_sizes, int n_in,
                              void* d_out, int out_size) {
    const float* sup = (const float*)d_in[0];
    const float* qry = (const float*)d_in[1];
    float* out = (float*)d_out;
    (void)in_sizes; (void)n_in; (void)out_size;

    cudaFuncSetAttribute(cross_mma, cudaFuncAttributeMaxDynamicSharedMemorySize, X_SMEM);
    cudaFuncSetAttribute(self_mma,  cudaFuncAttributeMaxDynamicSharedMemorySize, S_SMEM);

    zero_kernel<<<24, 256>>>();
    norm_kernel<<<(SRN + TRN + 7) / 8, 256>>>(sup, qry);
    self_mma<<<320, 288, S_SMEM>>>();
    cross_mma<<<NB * 6 * 15, 256, X_SMEM>>>();   // 4th launch -> ncu capture
    combine_kernel<<<(NB * NQQ * NWAY + 127) / 128, 128>>>(out);
}

// round 6
// speedup vs baseline: 1.1741x; 1.1741x over previous
#include <cuda_runtime.h>
#include <cuda_fp16.h>
#include <cstdint>

#define NB   16
#define NWAY 5
#define NQ   25
#define NSS  130
#define NQQ  75
#define CF   640
#define KK   1280            // K-concat stream length (hi|ps)
#define SRN  (NB*NWAY*NSS)   // 10400
#define TRN  (NB*NQQ*NQ)     // 30000
#define ROWB (KK*2)          // 2560 B per row
#define RS   144             // smem row stride (128B data + 16 pad)
#define NCH  20              // chunks of 64 fp16

__device__ __half g_S[SRN*KK];
__device__ __half g_T[TRN*KK];
__device__ float g_ss_sum[NB*NWAY];
__device__ float g_mmd_q[NB*NQQ];
__device__ float g_qs_sum[NB*NQQ*NWAY];

// ---------------------------------------------------------------------------
__device__ __forceinline__ uint32_t smem_u32(const void* p) {
    uint32_t a;
    asm("{ .reg .u64 t; cvta.to.shared.u64 t, %1; cvt.u32.u64 %0, t; }"
        : "=r"(a) : "l"(p));
    return a;
}
__device__ __forceinline__ void ldsm_x4(uint32_t* r, uint32_t addr) {
    asm volatile("ldmatrix.sync.aligned.m8n8.x4.shared.b16 {%0,%1,%2,%3}, [%4];"
                 : "=r"(r[0]), "=r"(r[1]), "=r"(r[2]), "=r"(r[3]) : "r"(addr));
}
__device__ __forceinline__ void mma4(float* c, const uint32_t* a,
                                     uint32_t b0, uint32_t b1) {
    asm volatile(
        "mma.sync.aligned.m16n8k16.row.col.f32.f16.f16.f32 "
        "{%0,%1,%2,%3}, {%4,%5,%6,%7}, {%8,%9}, {%0,%1,%2,%3};"
        : "+f"(c[0]), "+f"(c[1]), "+f"(c[2]), "+f"(c[3])
        : "r"(a[0]), "r"(a[1]), "r"(a[2]), "r"(a[3]), "r"(b0), "r"(b1));
}
__device__ __forceinline__ void cp16(uint32_t dst, const void* src, int szp) {
    asm volatile("cp.async.cg.shared.global [%0], [%1], 16, %2;"
                 :: "r"(dst), "l"(src), "r"(szp));
}
#define CP_COMMIT() asm volatile("cp.async.commit_group;" ::: "memory")
#define CP_WAIT1()  asm volatile("cp.async.wait_group 1;" ::: "memory")
#define CP_WAIT0()  asm volatile("cp.async.wait_group 0;" ::: "memory")

// dot = acc*1024/1025 ; d2 = 2 - 2*dot
__device__ __forceinline__ float multigauss_acc(float acc) {
    float d2 = fmaxf(2.0f - 1.9980487804878049f * acc, 0.0f);
    float u  = __expf(-0.125f * d2);
    float u2 = u*u, u4 = u2*u2, u8 = u4*u4, u16 = u8*u8;
    return u + u2 + u4 + u8 + u16;
}

// ---------------------------------------------------------------------------
__global__ void zero_kernel() {
    int t = blockIdx.x * blockDim.x + threadIdx.x;
    if (t < NB * NQQ * NWAY) g_qs_sum[t] = 0.f;
}

// normalize: one warp per row; emit K-concat [hi(640)|ps(640)] fp16
__global__ __launch_bounds__(256) void norm_kernel(
    const float* __restrict__ sup, const float* __restrict__ qry) {
    int row = blockIdx.x * 8 + (threadIdx.x >> 5);
    if (row >= SRN + TRN) return;
    int lane = threadIdx.x & 31;

    const float* src;
    __half* dst;
    if (row < SRN) {
        src = sup + (size_t)row * CF;
        dst = g_S + (size_t)row * KK;
    } else {
        int r = row - SRN;
        src = qry + (size_t)r * CF;
        dst = g_T + (size_t)r * KK;
    }

    float4 v[5];
    float s1 = 0.f, s2 = 0.f;
#pragma unroll
    for (int s = 0; s < 5; s++) {
        v[s] = ((const float4*)src)[s * 32 + lane];
        s1 += v[s].x + v[s].y + v[s].z + v[s].w;
        s2 += v[s].x*v[s].x + v[s].y*v[s].y + v[s].z*v[s].z + v[s].w*v[s].w;
    }
#pragma unroll
    for (int o = 16; o > 0; o >>= 1) {
        s1 += __shfl_xor_sync(0xffffffffu, s1, o);
        s2 += __shfl_xor_sync(0xffffffffu, s2, o);
    }
    float mean = s1 * (1.0f / CF);
    float inv = rsqrtf(s2 - s1 * mean + 1e-12f);

#pragma unroll
    for (int s = 0; s < 5; s++) {
        float x[4] = {(v[s].x - mean) * inv, (v[s].y - mean) * inv,
                      (v[s].z - mean) * inv, (v[s].w - mean) * inv};
        union { __half h[4]; uint2 u; } ph, pp;
#pragma unroll
        for (int k = 0; k < 4; k++) {
            __half hh = __float2half_rn(x[k]);
            float h = __half2float(hh);
            ph.h[k] = hh;
            float P = h + 1024.0f * (x[k] - h);
            pp.h[k] = __float2half_rn(P * 0.03125f);
        }
        ((uint2*)dst)[s * 32 + lane] = ph.u;
        ((uint2*)(dst + CF))[s * 32 + lane] = pp.u;
    }
}

// ---------------------------------------------------------------------------
// cross Gram: CTA 128x128, 8 warps 4x2 (warp 32x64), K=1280
// 2-stage cp.async (chunk 64 fp16), register-double-buffered fragments
#define X_ARR   (128*RS)           // 18432
#define X_STAGE (2*X_ARR)          // 36864
#define X_SMEM  (2*X_STAGE)        // 73728

__global__ __launch_bounds__(256, 2) void cross_mma() {
    extern __shared__ char smem[];
    __shared__ float tab[16];
    uint32_t sb = smem_u32(smem);
    int tid = threadIdx.x, lane = tid & 31, wid = tid >> 5;
    int wm = wid >> 1, wn = wid & 1;
    int gid = lane >> 2, tig = lane & 3;

    int bx = blockIdx.x;
    int nt_t = bx % 15;
    int mt_t = (bx / 15) % 6;
    int b    = bx / 90;

    int aValid = 650 - mt_t * 128; if (aValid > 128) aValid = 128;
    int bValid = 1875 - nt_t * 128; if (bValid > 128) bValid = 128;
    const char* A = (const char*)(g_S + ((size_t)b * 650 + mt_t * 128) * KK);
    const char* B = (const char*)(g_T + ((size_t)b * 1875 + nt_t * 128) * KK);

    if (tid < 16) tab[tid] = 0.f;

    float acc[2][8][4];
#pragma unroll
    for (int i = 0; i < 2; i++)
#pragma unroll
        for (int j = 0; j < 8; j++)
#pragma unroll
            for (int k = 0; k < 4; k++) acc[i][j][k] = 0.f;

    int lrow = lane & 15, lcol = (lane >> 4) << 4;
    // per-warp ldsm base offsets (within array)
    uint32_t aoff = (wm * 32 + lrow) * RS + lcol;
    uint32_t boff = (wn * 64 + lrow) * RS + lcol;

    auto fill = [&](int stage, int c) {
#pragma unroll
        for (int it = 0; it < 8; it++) {
            int idx = tid + it * 256;          // 0..2047
            int arr = idx >> 10;               // 0:A 1:B
            int rs  = idx & 1023;
            int row = rs >> 3, seg = rs & 7;
            const char* base = arr ? B : A;
            int valid = arr ? bValid : aValid;
            cp16(sb + stage * X_STAGE + arr * X_ARR + row * RS + seg * 16,
                 base + (size_t)row * ROWB + c * 128 + seg * 16,
                 row < valid ? 16 : 0);
        }
        CP_COMMIT();
    };

    uint32_t af[2][2][4], bf[2][4][4];

    auto ldfrag = [&](uint32_t base, int buf, int ks) {
#pragma unroll
        for (int mt = 0; mt < 2; mt++)
            ldsm_x4(af[buf][mt], base + aoff + mt * (16 * RS) + ks * 32);
#pragma unroll
        for (int p = 0; p < 4; p++)
            ldsm_x4(bf[buf][p], base + X_ARR + boff + p * (16 * RS) + ks * 32);
    };

    fill(0, 0);
    fill(1, 1);
    for (int c = 0; c < NCH; c++) {
        if (c == NCH - 1) { CP_WAIT0(); } else { CP_WAIT1(); }
        __syncthreads();
        uint32_t base = sb + (c & 1) * X_STAGE;
        ldfrag(base, 0, 0);
#pragma unroll
        for (int ks = 0; ks < 4; ks++) {
            int cur = ks & 1;
            if (ks < 3) ldfrag(base, cur ^ 1, ks + 1);
#pragma unroll
            for (int p = 0; p < 4; p++)
#pragma unroll
                for (int mt = 0; mt < 2; mt++) {
                    mma4(acc[mt][p*2+0], af[cur][mt], bf[cur][p][0], bf[cur][p][2]);
                    mma4(acc[mt][p*2+1], af[cur][mt], bf[cur][p][1], bf[cur][p][3]);
                }
        }
        __syncthreads();
        if (c + 2 < NCH) fill((c & 1), c + 2);
    }

    // epilogue: multigauss + (w,q) bucket reduction
    int qb = nt_t * 128;
    int q_base = qb / 25;
    int w_base = (mt_t * 128) / 130;
#pragma unroll
    for (int mt = 0; mt < 2; mt++)
#pragma unroll
    for (int rh = 0; rh < 2; rh++) {
        int row = wm * 32 + mt * 16 + rh * 8 + gid;
        int gs = mt_t * 128 + row;
        if (gs < 650) {
            int wrel = gs / 130 - w_base;
            float run = 0.f;
            int qprev = (qb + wn * 64 + tig * 2) / 25;
#pragma unroll
            for (int nt = 0; nt < 8; nt++)
#pragma unroll
            for (int e = 0; e < 2; e++) {
                int gt = qb + wn * 64 + nt * 8 + tig * 2 + e;
                int q = gt / 25;
                if (q != qprev) {
                    atomicAdd(&tab[wrel * 8 + (qprev - q_base)], run);
                    run = 0.f; qprev = q;
                }
                if (gt < 1875) run += multigauss_acc(acc[mt][nt][rh * 2 + e]);
            }
            atomicAdd(&tab[wrel * 8 + (qprev - q_base)], run);
        }
    }
    __syncthreads();
    if (tid < 16) {
        float v = tab[tid];
        if (v != 0.f) {
            int q = q_base + (tid & 7);
            int w = w_base + (tid >> 3);
            if (q < NQQ && w < NWAY)
                atomicAdd(&g_qs_sum[(b * NQQ + q) * NWAY + w], v);
        }
    }
}

// ---------------------------------------------------------------------------
// fused self Grams: blocks [0,80) -> kss (288 thr), [80,320) -> kqq (160 thr)
#define SRT    144
#define S_STAGE (SRT*RS)           // 20736
#define S_SMEM  (2*S_STAGE)        // 41472
#define QRT    132
#define Q_STAGE (QRT*RS)           // 19008

__global__ __launch_bounds__(288) void self_mma() {
    extern __shared__ char smem[];
    __shared__ float red[9];
    uint32_t sb = smem_u32(smem);
    int tid = threadIdx.x, lane = tid & 31, wid = tid >> 5;
    int gid = lane >> 2, tig = lane & 3;
    int lrow = lane & 15, lcol = (lane >> 4) << 4;

    if (blockIdx.x < 80) {
        // ---- kss: CTA per (b,w); 9 warps 3x3, warp tile 48x48 ----
        int b = blockIdx.x / NWAY, w = blockIdx.x % NWAY;
        int wm = wid / 3, wn = wid % 3;
        const char* H = (const char*)(g_S + ((size_t)(b * NWAY + w) * NSS) * KK);

        for (int idx = tid; idx < 2 * 14 * 9; idx += 288) {
            int st = idx / 126, rr = (idx % 126) / 9, sg = idx % 9;
            *(uint4*)(smem + st * S_STAGE + (130 + rr) * RS + sg * 16)
                = make_uint4(0,0,0,0);
        }
        __syncthreads();

        float acc[3][6][4];
#pragma unroll
        for (int i = 0; i < 3; i++)
#pragma unroll
            for (int j = 0; j < 6; j++)
#pragma unroll
                for (int k = 0; k < 4; k++) acc[i][j][k] = 0.f;

        uint32_t aoff = (wm * 48 + lrow) * RS + lcol;
        uint32_t boff = (wn * 48 + lrow) * RS + lcol;

        auto fill = [&](int stage, int c) {
#pragma unroll
            for (int it = 0; it < 4; it++) {
                int idx = tid + it * 288;      // tasks 1040
                if (idx < 1040) {
                    int row = idx >> 3, seg = idx & 7;
                    cp16(sb + stage * S_STAGE + row * RS + seg * 16,
                         H + (size_t)row * ROWB + c * 128 + seg * 16, 16);
                }
            }
            CP_COMMIT();
        };

        uint32_t af[2][3][4], bf[2][3][4];
        auto ldfrag = [&](uint32_t base, int buf, int ks) {
#pragma unroll
            for (int mt = 0; mt < 3; mt++)
                ldsm_x4(af[buf][mt], base + aoff + mt * (16 * RS) + ks * 32);
#pragma unroll
            for (int p = 0; p < 3; p++)
                ldsm_x4(bf[buf][p], base + boff + p * (16 * RS) + ks * 32);
        };

        fill(0, 0); fill(1, 1);
        for (int c = 0; c < NCH; c++) {
            if (c == NCH - 1) { CP_WAIT0(); } else { CP_WAIT1(); }
            __syncthreads();
            uint32_t base = sb + (c & 1) * S_STAGE;
            ldfrag(base, 0, 0);
#pragma unroll
            for (int ks = 0; ks < 4; ks++) {
                int cur = ks & 1;
                if (ks < 3) ldfrag(base, cur ^ 1, ks + 1);
#pragma unroll
                for (int p = 0; p < 3; p++)
#pragma unroll
                    for (int mt = 0; mt < 3; mt++) {
                        mma4(acc[mt][p*2+0], af[cur][mt], bf[cur][p][0], bf[cur][p][2]);
                        mma4(acc[mt][p*2+1], af[cur][mt], bf[cur][p][1], bf[cur][p][3]);
                    }
            }
            __syncthreads();
            if (c + 2 < NCH) fill((c & 1), c + 2);
        }

        float sum = 0.f;
#pragma unroll
        for (int mt = 0; mt < 3; mt++)
#pragma unroll
        for (int nt = 0; nt < 6; nt++)
#pragma unroll
        for (int rh = 0; rh < 2; rh++)
#pragma unroll
        for (int e = 0; e < 2; e++) {
            int row = wm * 48 + mt * 16 + rh * 8 + gid;
            int col = wn * 48 + nt * 8 + tig * 2 + e;
            if (row < NSS && col < NSS && row != col)
                sum += multigauss_acc(acc[mt][nt][rh * 2 + e]);
        }
#pragma unroll
        for (int o = 16; o > 0; o >>= 1) sum += __shfl_down_sync(0xffffffffu, sum, o);
        if (lane == 0) red[wid] = sum;
        __syncthreads();
        if (tid == 0) {
            float t = 0.f;
            for (int i = 0; i < 9; i++) t += red[i];
            g_ss_sum[b * NWAY + w] = t;
        }
    } else {
        // ---- kqq: CTA per (b, 5-q group); warps 0..4 -> diag 25x25 blocks ----
        if (tid >= 160) return;
        int p = blockIdx.x - 80;
        int b = p / 15, qg = p % 15;
        const char* H = (const char*)(g_T + ((size_t)b * 1875 + qg * 125) * KK);

        for (int idx = tid; idx < 2 * 7 * 9; idx += 160) {
            int st = idx / 63, rr = (idx % 63) / 9, sg = idx % 9;
            *(uint4*)(smem + st * Q_STAGE + (125 + rr) * RS + sg * 16)
                = make_uint4(0,0,0,0);
        }
        __syncthreads();

        float acc[2][4][4];
#pragma unroll
        for (int i = 0; i < 2; i++)
#pragma unroll
            for (int j = 0; j < 4; j++)
#pragma unroll
                for (int k = 0; k < 4; k++) acc[i][j][k] = 0.f;

        uint32_t woff = (wid * 25 + lrow) * RS + lcol;

        auto fill = [&](int stage, int c) {
#pragma unroll
            for (int it = 0; it < 7; it++) {
                int idx = tid + it * 160;      // tasks 1000
                if (idx < 1000) {
                    int row = idx >> 3, seg = idx & 7;
                    cp16(sb + stage * Q_STAGE + row * RS + seg * 16,
                         H + (size_t)row * ROWB + c * 128 + seg * 16, 16);
                }
            }
            CP_COMMIT();
        };

        uint32_t af[2][2][4];
        auto ldfrag = [&](uint32_t base, int buf, int ks) {
#pragma unroll
            for (int mt = 0; mt < 2; mt++)
                ldsm_x4(af[buf][mt], base + woff + mt * (16 * RS) + ks * 32);
        };

        fill(0, 0); fill(1, 1);
        for (int c = 0; c < NCH; c++) {
            if (c == NCH - 1) { CP_WAIT0(); } else { CP_WAIT1(); }
            __syncthreads();
            uint32_t base = sb + (c & 1) * Q_STAGE;
            ldfrag(base, 0, 0);
#pragma unroll
            for (int ks = 0; ks < 4; ks++) {
                int cur = ks & 1;
                if (ks < 3) ldfrag(base, cur ^ 1, ks + 1);
#pragma unroll
                for (int pp = 0; pp < 2; pp++)
#pragma unroll
                    for (int mt = 0; mt < 2; mt++) {
                        mma4(acc[mt][pp*2+0], af[cur][mt], af[cur][pp][0], af[cur][pp][2]);
                        mma4(acc[mt][pp*2+1], af[cur][mt], af[cur][pp][1], af[cur][pp][3]);
                    }
            }
            __syncthreads();
            if (c + 2 < NCH) fill((c & 1), c + 2);
        }

        float sum = 0.f;
#pragma unroll
        for (int mt = 0; mt < 2; mt++)
#pragma unroll
        for (int nt = 0; nt < 4; nt++)
#pragma unroll
        for (int rh = 0; rh < 2; rh++)
#pragma unroll
        for (int e = 0; e < 2; e++) {
            int row = mt * 16 + rh * 8 + gid;
            int col = nt * 8 + tig * 2 + e;
            if (row < NQ && col < NQ && row != col)
                sum += multigauss_acc(acc[mt][nt][rh * 2 + e]);
        }
#pragma unroll
        for (int o = 16; o > 0; o >>= 1) sum += __shfl_down_sync(0xffffffffu, sum, o);
        if (lane == 0)
            g_mmd_q[b * NQQ + qg * 5 + wid] = sum * (1.0f / (NQ * (NQ - 1)));
    }
}

// ---------------------------------------------------------------------------
__global__ void combine_kernel(float* __restrict__ out) {
    int idx = blockIdx.x * blockDim.x + threadIdx.x;
    if (idx >= NB * NQQ * NWAY) return;
    int w = idx % NWAY;
    int bq = idx / NWAY;
    int b = bq / NQQ;
    out[idx] = g_ss_sum[b * NWAY + w] * (1.0f / (NSS * (NSS - 1)))
             + g_mmd_q[bq]
             - 2.0f * g_qs_sum[idx] * (1.0f / (NSS * NQ));
}

// ---------------------------------------------------------------------------
extern "C" void kernel_launch(void* const* d_in, const int* in_sizes, int n_in,
                              void* d_out, int out_size) {
    const float* sup = (const float*)d_in[0];
    const float* qry = (const float*)d_in[1];
    float* out = (float*)d_out;
    (void)in_sizes; (void)n_in; (void)out_size;

    cudaFuncSetAttribute(cross_mma, cudaFuncAttributeMaxDynamicSharedMemorySize, X_SMEM);
    cudaFuncSetAttribute(self_mma,  cudaFuncAttributeMaxDynamicSharedMemorySize, S_SMEM);

    zero_kernel<<<24, 256>>>();
    norm_kernel<<<(SRN + TRN + 7) / 8, 256>>>(sup, qry);
    self_mma<<<320, 288, S_SMEM>>>();
    cross_mma<<<NB * 6 * 15, 256, X_SMEM>>>();   // 4th launch -> ncu capture
    combine_kernel<<<(NB * NQQ * NWAY + 127) / 128, 128>>>(out);
}